// round 2
// baseline (speedup 1.0000x reference)
#include <cuda_runtime.h>
#include <math.h>

#define BB 1323u            // batch == NPTS
#define DM 1024             // DMODEL
#define NTOT (BB * BB)      // 1,750,329 points
#define LOG_2PI 1.8378770664093453f

// params scratch: 16 floats per row, 16B-aligned rows
__device__ __align__(16) float g_params[BB * 16];

__device__ __forceinline__ float softplus_f(float x) {
    return fmaxf(x, 0.0f) + log1pf(__expf(-fabsf(x)));
}

// ---------------- kernel 1: per-row params (warp per row) ----------------
__global__ __launch_bounds__(256)
void mvn3d_params_kernel(const float* __restrict__ rep,
                         const float* __restrict__ Wm,
                         const float* __restrict__ bm,
                         const float* __restrict__ Ws,
                         const float* __restrict__ bs,
                         float* __restrict__ out)
{
    const int warp = threadIdx.x >> 5;
    const int lane = threadIdx.x & 31;
    const unsigned row = blockIdx.x * 8 + warp;
    if (row >= BB) return;

    float acc[9];
    #pragma unroll
    for (int a = 0; a < 9; a++) acc[a] = 0.0f;

    const float* r = rep + (size_t)row * DM;
    #pragma unroll 4
    for (int k = lane; k < DM; k += 32) {
        float rv = r[k];
        acc[0] = fmaf(rv, Wm[k],          acc[0]);
        acc[1] = fmaf(rv, Wm[DM + k],     acc[1]);
        acc[2] = fmaf(rv, Wm[2*DM + k],   acc[2]);
        acc[3] = fmaf(rv, Ws[k],          acc[3]);
        acc[4] = fmaf(rv, Ws[DM + k],     acc[4]);
        acc[5] = fmaf(rv, Ws[2*DM + k],   acc[5]);
        acc[6] = fmaf(rv, Ws[3*DM + k],   acc[6]);
        acc[7] = fmaf(rv, Ws[4*DM + k],   acc[7]);
        acc[8] = fmaf(rv, Ws[5*DM + k],   acc[8]);
    }

    #pragma unroll
    for (int a = 0; a < 9; a++) {
        #pragma unroll
        for (int off = 16; off > 0; off >>= 1)
            acc[a] += __shfl_down_sync(0xffffffffu, acc[a], off);
    }

    if (lane == 0) {
        float mx  = acc[0] + bm[0];
        float my  = acc[1] + bm[1];
        float mz  = acc[2] + bm[2];
        float L00 = softplus_f(acc[3] + bs[0]);
        float L10 = acc[4] + bs[1];
        float L11 = softplus_f(acc[5] + bs[2]);
        float L20 = acc[6] + bs[3];
        float L21 = acc[7] + bs[4];
        float L22 = softplus_f(acc[8] + bs[5]);

        float c = -(logf(L00) + logf(L11) + logf(L22)) - 1.5f * LOG_2PI;

        float4* P = (float4*)(g_params + (size_t)row * 16);
        P[0] = make_float4(mx, my, mz, 1.0f / L00);
        P[1] = make_float4(L10, 1.0f / L11, L20, L21);
        P[2] = make_float4(1.0f / L22, c, 0.0f, 0.0f);

        float* Lout = out + (size_t)NTOT + (size_t)row * 9;
        Lout[0] = L00; Lout[1] = 0.0f; Lout[2] = 0.0f;
        Lout[3] = L10; Lout[4] = L11; Lout[5] = 0.0f;
        Lout[6] = L20; Lout[7] = L21; Lout[8] = L22;
    }
}

// ---------------- kernel 2: linear stream, 4 points/thread ----------------
__device__ __forceinline__ float mvn_eval(float d0, float d1, float d2,
                                          const float4& P0, const float4& P1,
                                          const float4& P2)
{
    float y0 = (d0 - P0.x) * P0.w;
    float y1 = (d1 - P0.y - P1.x * y0) * P1.y;
    float y2 = (d2 - P0.z - P1.z * y0 - P1.w * y1) * P2.x;
    float M  = fmaf(y0, y0, fmaf(y1, y1, y2 * y2));
    return __expf(fmaf(-0.5f, M, P2.y));
}

__global__ __launch_bounds__(256)
void mvn3d_profile_kernel(const float* __restrict__ dxyz,
                          float* __restrict__ out)
{
    const unsigned t  = blockIdx.x * blockDim.x + threadIdx.x;
    const unsigned p0 = t * 4;
    if (p0 >= NTOT) return;

    if (p0 + 3 < NTOT) {
        // 12 contiguous floats, 16B-aligned (48B per thread)
        const float4* dv = (const float4*)(dxyz + (size_t)p0 * 3);
        float4 a = dv[0], b = dv[1], c4 = dv[2];
        float d[12] = {a.x, a.y, a.z, a.w, b.x, b.y, b.z, b.w,
                       c4.x, c4.y, c4.z, c4.w};

        float4 res;
        float* rp = &res.x;

        unsigned iprev = 0xffffffffu;
        float4 P0, P1, P2;
        #pragma unroll
        for (int k = 0; k < 4; k++) {
            unsigned p = p0 + k;
            unsigned i = p / BB;          // const-div -> mul+shift
            if (i != iprev) {
                const float4* P = (const float4*)(g_params + (size_t)i * 16);
                P0 = P[0]; P1 = P[1]; P2 = P[2];
                iprev = i;
            }
            rp[k] = mvn_eval(d[3*k], d[3*k+1], d[3*k+2], P0, P1, P2);
        }
        *(float4*)(out + p0) = res;
    } else {
        // tail (< 4 points)
        for (unsigned p = p0; p < NTOT; p++) {
            unsigned i = p / BB;
            const float4* P = (const float4*)(g_params + (size_t)i * 16);
            float4 P0 = P[0], P1 = P[1], P2 = P[2];
            float d0 = dxyz[3*p], d1 = dxyz[3*p+1], d2 = dxyz[3*p+2];
            out[p] = mvn_eval(d0, d1, d2, P0, P1, P2);
        }
    }
}

extern "C" void kernel_launch(void* const* d_in, const int* in_sizes, int n_in,
                              void* d_out, int out_size) {
    const float* rep  = (const float*)d_in[0];
    const float* dxyz = (const float*)d_in[1];
    const float* Wm   = (const float*)d_in[2];
    const float* bm   = (const float*)d_in[3];
    const float* Ws   = (const float*)d_in[4];
    const float* bs   = (const float*)d_in[5];
    float* out = (float*)d_out;

    mvn3d_params_kernel<<<(BB + 7) / 8, 256>>>(rep, Wm, bm, Ws, bs, out);

    const unsigned nthreads_total = (NTOT + 3) / 4;            // 437,583
    const unsigned nblocks = (nthreads_total + 255) / 256;     // 1710
    mvn3d_profile_kernel<<<nblocks, 256>>>(dxyz, out);
}

// round 3
// speedup vs baseline: 1.2772x; 1.2772x over previous
#include <cuda_runtime.h>
#include <math.h>

#define BB 1323u            // batch == NPTS
#define DM 1024             // DMODEL
#define NTOT (BB * BB)      // 1,750,329 points
#define LOG_2PI 1.8378770664093453f

// params scratch: 16 floats per row, 16B-aligned rows
__device__ __align__(16) float g_params[BB * 16];

__device__ __forceinline__ float softplus_f(float x) {
    return fmaxf(x, 0.0f) + log1pf(__expf(-fabsf(x)));
}

// ---------------- kernel 1: per-row params, weights staged in smem ----------------
// 8 rows per block (warp per row); 166 blocks.
__global__ __launch_bounds__(256)
void mvn3d_params_kernel(const float* __restrict__ rep,
                         const float* __restrict__ Wm,
                         const float* __restrict__ bm,
                         const float* __restrict__ Ws,
                         const float* __restrict__ bs,
                         float* __restrict__ out)
{
    __shared__ __align__(16) float sW[9 * DM];       // 36 KB: Wm rows 0..2, Ws rows 0..5
    float4* sW4 = (float4*)sW;

    const int tid  = threadIdx.x;
    const int warp = tid >> 5;
    const int lane = tid & 31;

    // cooperative weight load: 2304 float4 total, 9 per thread
    {
        const float4* Wm4 = (const float4*)Wm;   // 768 float4
        const float4* Ws4 = (const float4*)Ws;   // 1536 float4
        #pragma unroll
        for (int c = 0; c < 9; c++) {
            int t2 = c * 256 + tid;
            sW4[t2] = (t2 < 768) ? Wm4[t2] : Ws4[t2 - 768];
        }
    }
    __syncthreads();

    const unsigned row = blockIdx.x * 8 + warp;
    if (row >= BB) return;

    float acc[9];
    #pragma unroll
    for (int a = 0; a < 9; a++) acc[a] = 0.0f;

    const float4* r4 = (const float4*)(rep + (size_t)row * DM);  // 256 float4
    #pragma unroll
    for (int c = 0; c < 8; c++) {
        int idx = c * 32 + lane;
        float4 rv = r4[idx];
        #pragma unroll
        for (int a = 0; a < 9; a++) {
            float4 w = sW4[a * 256 + idx];
            acc[a] = fmaf(rv.x, w.x, fmaf(rv.y, w.y, fmaf(rv.z, w.z, fmaf(rv.w, w.w, acc[a]))));
        }
    }

    #pragma unroll
    for (int a = 0; a < 9; a++) {
        #pragma unroll
        for (int off = 16; off > 0; off >>= 1)
            acc[a] += __shfl_down_sync(0xffffffffu, acc[a], off);
    }

    if (lane == 0) {
        float mx  = acc[0] + bm[0];
        float my  = acc[1] + bm[1];
        float mz  = acc[2] + bm[2];
        float L00 = softplus_f(acc[3] + bs[0]);
        float L10 = acc[4] + bs[1];
        float L11 = softplus_f(acc[5] + bs[2]);
        float L20 = acc[6] + bs[3];
        float L21 = acc[7] + bs[4];
        float L22 = softplus_f(acc[8] + bs[5]);

        float c = -(logf(L00) + logf(L11) + logf(L22)) - 1.5f * LOG_2PI;

        float4* P = (float4*)(g_params + (size_t)row * 16);
        P[0] = make_float4(mx, my, mz, 1.0f / L00);
        P[1] = make_float4(L10, 1.0f / L11, L20, L21);
        P[2] = make_float4(1.0f / L22, c, 0.0f, 0.0f);

        float* Lout = out + (size_t)NTOT + (size_t)row * 9;
        Lout[0] = L00; Lout[1] = 0.0f; Lout[2] = 0.0f;
        Lout[3] = L10; Lout[4] = L11; Lout[5] = 0.0f;
        Lout[6] = L20; Lout[7] = L21; Lout[8] = L22;
    }
}

// ---------------- kernel 2: linear stream, 8 points/thread ----------------
__device__ __forceinline__ float mvn_eval(float d0, float d1, float d2,
                                          const float4& P0, const float4& P1,
                                          const float4& P2)
{
    float y0 = (d0 - P0.x) * P0.w;
    float y1 = (d1 - P0.y - P1.x * y0) * P1.y;
    float y2 = (d2 - P0.z - P1.z * y0 - P1.w * y1) * P2.x;
    float M  = fmaf(y0, y0, fmaf(y1, y1, y2 * y2));
    return __expf(fmaf(-0.5f, M, P2.y));
}

__global__ __launch_bounds__(256)
void mvn3d_profile_kernel(const float* __restrict__ dxyz,
                          float* __restrict__ out)
{
    const unsigned t  = blockIdx.x * blockDim.x + threadIdx.x;
    const unsigned p0 = t * 8;
    if (p0 >= NTOT) return;

    if (p0 + 7 < NTOT) {
        // 24 contiguous floats, 96B-aligned: 6x LDG.128 front-batched
        const float4* dv = (const float4*)(dxyz + (size_t)p0 * 3);
        float4 v[6];
        #pragma unroll
        for (int c = 0; c < 6; c++) v[c] = dv[c];
        const float* d = (const float*)v;

        unsigned i = p0 / BB;             // one const-divide per thread
        unsigned j = p0 - i * BB;
        const float4* P = (const float4*)(g_params + (size_t)i * 16);
        float4 P0 = P[0], P1 = P[1], P2 = P[2];

        float res[8];
        #pragma unroll
        for (int k = 0; k < 8; k++) {
            if (j >= BB) {                // at most once per thread
                j -= BB;
                i++;
                P = (const float4*)(g_params + (size_t)i * 16);
                P0 = P[0]; P1 = P[1]; P2 = P[2];
            }
            res[k] = mvn_eval(d[3*k], d[3*k+1], d[3*k+2], P0, P1, P2);
            j++;
        }

        float4* ov = (float4*)(out + p0);
        ov[0] = make_float4(res[0], res[1], res[2], res[3]);
        ov[1] = make_float4(res[4], res[5], res[6], res[7]);
    } else {
        // tail (< 8 points)
        for (unsigned p = p0; p < NTOT; p++) {
            unsigned i = p / BB;
            const float4* P = (const float4*)(g_params + (size_t)i * 16);
            float4 P0 = P[0], P1 = P[1], P2 = P[2];
            out[p] = mvn_eval(dxyz[3*p], dxyz[3*p+1], dxyz[3*p+2], P0, P1, P2);
        }
    }
}

extern "C" void kernel_launch(void* const* d_in, const int* in_sizes, int n_in,
                              void* d_out, int out_size) {
    const float* rep  = (const float*)d_in[0];
    const float* dxyz = (const float*)d_in[1];
    const float* Wm   = (const float*)d_in[2];
    const float* bm   = (const float*)d_in[3];
    const float* Ws   = (const float*)d_in[4];
    const float* bs   = (const float*)d_in[5];
    float* out = (float*)d_out;

    mvn3d_params_kernel<<<(BB + 7) / 8, 256>>>(rep, Wm, bm, Ws, bs, out);

    const unsigned nthreads_total = (NTOT + 7) / 8;            // 218,792
    const unsigned nblocks = (nthreads_total + 255) / 256;     // 855
    mvn3d_profile_kernel<<<nblocks, 256>>>(dxyz, out);
}

// round 6
// speedup vs baseline: 1.2829x; 1.0045x over previous
#include <cuda_runtime.h>
#include <math.h>

#define BB 1323u            // batch == NPTS
#define DM 1024             // DMODEL
#define NTOT (BB * BB)      // 1,750,329 points
#define NCHUNK ((NTOT + 3) / 4)       // 437,583 4-point chunks
#define NBLK 1184u                    // 8 CTAs/SM * 148 SMs
#define TPB 256u
#define TTOT (NBLK * TPB)             // 303,104 threads
#define LOG_2PI 1.8378770664093453f

__device__ __align__(16) float g_params[BB * 16];

__device__ __forceinline__ float softplus_f(float x) {
    return fmaxf(x, 0.0f) + log1pf(__expf(-fabsf(x)));
}

// ---------------- kernel 1: per-row params, weights staged in smem ----------------
__global__ __launch_bounds__(256)
void mvn3d_params_kernel(const float* __restrict__ rep,
                         const float* __restrict__ Wm,
                         const float* __restrict__ bm,
                         const float* __restrict__ Ws,
                         const float* __restrict__ bs,
                         float* __restrict__ out)
{
    __shared__ __align__(16) float sW[9 * DM];       // 36 KB
    float4* sW4 = (float4*)sW;

    const int tid  = threadIdx.x;
    const int warp = tid >> 5;
    const int lane = tid & 31;

    {
        const float4* Wm4 = (const float4*)Wm;   // 768 float4
        const float4* Ws4 = (const float4*)Ws;   // 1536 float4
        #pragma unroll
        for (int c = 0; c < 9; c++) {
            int t2 = c * 256 + tid;
            sW4[t2] = (t2 < 768) ? Wm4[t2] : Ws4[t2 - 768];
        }
    }
    __syncthreads();

    const unsigned row = blockIdx.x * 8 + warp;
    if (row >= BB) return;

    float acc[9];
    #pragma unroll
    for (int a = 0; a < 9; a++) acc[a] = 0.0f;

    const float4* r4 = (const float4*)(rep + (size_t)row * DM);
    #pragma unroll
    for (int c = 0; c < 8; c++) {
        int idx = c * 32 + lane;
        float4 rv = r4[idx];
        #pragma unroll
        for (int a = 0; a < 9; a++) {
            float4 w = sW4[a * 256 + idx];
            acc[a] = fmaf(rv.x, w.x, fmaf(rv.y, w.y, fmaf(rv.z, w.z, fmaf(rv.w, w.w, acc[a]))));
        }
    }

    #pragma unroll
    for (int a = 0; a < 9; a++) {
        #pragma unroll
        for (int off = 16; off > 0; off >>= 1)
            acc[a] += __shfl_down_sync(0xffffffffu, acc[a], off);
    }

    if (lane == 0) {
        float mx  = acc[0] + bm[0];
        float my  = acc[1] + bm[1];
        float mz  = acc[2] + bm[2];
        float L00 = softplus_f(acc[3] + bs[0]);
        float L10 = acc[4] + bs[1];
        float L11 = softplus_f(acc[5] + bs[2]);
        float L20 = acc[6] + bs[3];
        float L21 = acc[7] + bs[4];
        float L22 = softplus_f(acc[8] + bs[5]);

        float c = -(logf(L00) + logf(L11) + logf(L22)) - 1.5f * LOG_2PI;

        float4* P = (float4*)(g_params + (size_t)row * 16);
        P[0] = make_float4(mx, my, mz, 1.0f / L00);
        P[1] = make_float4(L10, 1.0f / L11, L20, L21);
        P[2] = make_float4(1.0f / L22, c, 0.0f, 0.0f);

        float* Lout = out + (size_t)NTOT + (size_t)row * 9;
        Lout[0] = L00; Lout[1] = 0.0f; Lout[2] = 0.0f;
        Lout[3] = L10; Lout[4] = L11; Lout[5] = 0.0f;
        Lout[6] = L20; Lout[7] = L21; Lout[8] = L22;
    }
}

// ---------------- kernel 2: two split 4-point chunks per thread ----------------
__device__ __forceinline__ float mvn_eval(float d0, float d1, float d2,
                                          const float4& P0, const float4& P1,
                                          const float4& P2)
{
    float y0 = (d0 - P0.x) * P0.w;
    float y1 = (d1 - P0.y - P1.x * y0) * P1.y;
    float y2 = (d2 - P0.z - P1.z * y0 - P1.w * y1) * P2.x;
    float M  = fmaf(y0, y0, fmaf(y1, y1, y2 * y2));
    return __expf(fmaf(-0.5f, M, P2.y));
}

// process one full 4-point chunk given preloaded 12 floats
__device__ __forceinline__ void chunk_eval(unsigned p0, const float* d,
                                           float* __restrict__ out)
{
    unsigned i = p0 / BB;
    unsigned j = p0 - i * BB;
    const float4* P = (const float4*)(g_params + (size_t)i * 16);
    float4 P0 = P[0], P1 = P[1], P2 = P[2];

    float4 res;
    float* rp = &res.x;
    #pragma unroll
    for (int k = 0; k < 4; k++) {
        if (j >= BB) {
            j -= BB;
            P = (const float4*)(g_params + (size_t)(++i) * 16);
            P0 = P[0]; P1 = P[1]; P2 = P[2];
        }
        rp[k] = mvn_eval(d[3*k], d[3*k+1], d[3*k+2], P0, P1, P2);
        j++;
    }
    *(float4*)(out + p0) = res;
}

// scalar tail (last partial chunk only)
__device__ __forceinline__ void tail_eval(unsigned pStart,
                                          const float* __restrict__ dxyz,
                                          float* __restrict__ out)
{
    for (unsigned p = pStart; p < NTOT; p++) {
        unsigned i = p / BB;
        const float4* P = (const float4*)(g_params + (size_t)i * 16);
        out[p] = mvn_eval(dxyz[3*p], dxyz[3*p+1], dxyz[3*p+2], P[0], P[1], P[2]);
    }
}

__global__ __launch_bounds__(TPB)
void mvn3d_profile_kernel(const float* __restrict__ dxyz,
                          float* __restrict__ out)
{
    const unsigned t = blockIdx.x * TPB + threadIdx.x;

    const unsigned pA = t * 4;                 // chunk 0
    const unsigned pB = (t + TTOT) * 4;        // chunk 1 (may not exist)

    const bool hasB  = (t + TTOT < NCHUNK);
    const bool fullA = (pA + 3 < NTOT);
    const bool fullB = hasB && (pB + 3 < NTOT);

    // front-batch all loads (up to 6x LDG.128)
    float4 vA[3], vB[3];
    if (fullA) {
        const float4* dv = (const float4*)(dxyz + (size_t)pA * 3);
        vA[0] = dv[0]; vA[1] = dv[1]; vA[2] = dv[2];
    }
    if (fullB) {
        const float4* dv = (const float4*)(dxyz + (size_t)pB * 3);
        vB[0] = dv[0]; vB[1] = dv[1]; vB[2] = dv[2];
    }

    if (fullA)           chunk_eval(pA, (const float*)vA, out);
    else if (pA < NTOT)  tail_eval(pA, dxyz, out);

    if (fullB)                   chunk_eval(pB, (const float*)vB, out);
    else if (hasB && pB < NTOT)  tail_eval(pB, dxyz, out);
}

extern "C" void kernel_launch(void* const* d_in, const int* in_sizes, int n_in,
                              void* d_out, int out_size) {
    const float* rep  = (const float*)d_in[0];
    const float* dxyz = (const float*)d_in[1];
    const float* Wm   = (const float*)d_in[2];
    const float* bm   = (const float*)d_in[3];
    const float* Ws   = (const float*)d_in[4];
    const float* bs   = (const float*)d_in[5];
    float* out = (float*)d_out;

    mvn3d_params_kernel<<<(BB + 7) / 8, 256>>>(rep, Wm, bm, Ws, bs, out);
    mvn3d_profile_kernel<<<NBLK, TPB>>>(dxyz, out);
}